// round 3
// baseline (speedup 1.0000x reference)
#include <cuda_runtime.h>
#include <cstdint>

// WeightedFeatureInteraction: out[b] = sum_{i<j} w[i,j] * <x[b,i,:], x[b,j,:]>
//   inputs: [B, F*D] fp32, F=64, D=128;  field_weights: [F,F] fp32;  out: [B,1] fp32
//
// Round 3: f32x2 lanes = adjacent j's (not adjacent d's). Weight pairs are
// stored packed {w_j, w_j+1} (no duplication), so ONE broadcast LDS.64 feeds
// TWO FFMA2s (the d0 and d1 chains). LDS wavefronts drop 2016 -> 1055/warp,
// co-saturating L1 and fma pipes instead of L1 capping fma at 50%.

#define NF 64
#define ND 128
#define THREADS 128

typedef unsigned long long u64;

__device__ __forceinline__ u64 ffma2(u64 a, u64 b, u64 c) {
    u64 d;
    asm("fma.rn.f32x2 %0, %1, %2, %3;" : "=l"(d) : "l"(a), "l"(b), "l"(c));
    return d;
}

__device__ __forceinline__ u64 pack2(float lo, float hi) {
    u64 d;
    asm("mov.b64 %0, {%1, %2};" : "=l"(d) : "f"(lo), "f"(hi));
    return d;
}

__device__ __forceinline__ float2 unpack2(u64 v) {
    float2 f;
    asm("mov.b64 {%0, %1}, %2;" : "=f"(f.x), "=f"(f.y) : "l"(v));
    return f;
}

__global__ void __launch_bounds__(THREADS, 3)
wfi_kernel(const float* __restrict__ inputs,
           const float* __restrict__ fw,
           float* __restrict__ out) {
    // wp[i][p] = {w[i][2p], w[i][2p+1]}, masked (j > i), packed. 16 KB.
    __shared__ u64 wp[NF][NF / 2];
    __shared__ float red[4];

    const int tid = threadIdx.x;

    for (int idx = tid; idx < NF * NF / 2; idx += THREADS) {
        int i = idx >> 5;
        int p = idx & 31;
        int j0 = 2 * p, j1 = 2 * p + 1;
        float w0 = (j0 > i) ? fw[i * NF + j0] : 0.0f;
        float w1 = (j1 > i) ? fw[i * NF + j1] : 0.0f;
        wp[i][p] = pack2(w0, w1);
    }
    __syncthreads();

    const int b = blockIdx.x * 2 + (tid >> 6);   // batch row
    const int q = tid & 63;                      // d-pair (d0 = 2q, d1 = 2q+1)

    const float* xb = inputs + (size_t)b * (NF * ND) + 2 * q;

    // Load v and transpose 2x2 into j-packed registers:
    //   ve[p] = {v_{2p}[d0], v_{2p+1}[d0]},  vo[p] = {v_{2p}[d1], v_{2p+1}[d1]}
    u64 ve[NF / 2], vo[NF / 2];
#pragma unroll
    for (int p = 0; p < NF / 2; ++p) {
        float2 a  = *(const float2*)(xb + (2 * p) * ND);       // coalesced LDG.64
        float2 b2 = *(const float2*)(xb + (2 * p + 1) * ND);
        ve[p] = pack2(a.x, b2.x);
        vo[p] = pack2(a.y, b2.y);
    }

    float acc0 = 0.0f, acc1 = 0.0f;
#pragma unroll
    for (int i = 0; i < NF - 1; ++i) {
        const int p0 = (i + 1) >> 1;   // first pair with any j > i (masked zeros absorb overlap)
        u64 t0 = 0ull, t1 = 0ull;
#pragma unroll
        for (int p = p0; p < NF / 2; ++p) {
            u64 w = wp[i][p];          // ONE broadcast LDS.64 ...
            t0 = ffma2(w, ve[p], t0);  // ... feeds TWO FFMA2s
            t1 = ffma2(w, vo[p], t1);
        }
        float2 t0f = unpack2(t0), t1f = unpack2(t1);
        float s0 = t0f.x + t0f.y;      // sum over j for d0
        float s1 = t1f.x + t1f.y;      // sum over j for d1
        float2 vie = unpack2(ve[i >> 1]);
        float2 vio = unpack2(vo[i >> 1]);
        float vi0 = (i & 1) ? vie.y : vie.x;   // v_i[d0]
        float vi1 = (i & 1) ? vio.y : vio.x;   // v_i[d1]
        acc0 = fmaf(vi0, s0, acc0);
        acc1 = fmaf(vi1, s1, acc1);
    }

    float s = acc0 + acc1;
#pragma unroll
    for (int off = 16; off > 0; off >>= 1)
        s += __shfl_xor_sync(0xFFFFFFFFu, s, off);

    const int wid = tid >> 5;
    if ((tid & 31) == 0) red[wid] = s;
    __syncthreads();

    if (tid == 0)  out[b] = red[0] + red[1];
    if (tid == 64) out[b] = red[2] + red[3];
}

extern "C" void kernel_launch(void* const* d_in, const int* in_sizes, int n_in,
                              void* d_out, int out_size) {
    const float* inputs = (const float*)d_in[0];
    const float* fw     = (const float*)d_in[1];
    float* out          = (float*)d_out;

    int B = in_sizes[0] / (NF * ND);
    wfi_kernel<<<B / 2, THREADS>>>(inputs, fw, out);
}

// round 5
// speedup vs baseline: 2.5048x; 2.5048x over previous
#include <cuda_runtime.h>
#include <cstdint>

// WeightedFeatureInteraction: out[b] = sum_{i<j} w[i,j] * <x[b,i,:], x[b,j,:]>
//   inputs [B, 64*128] fp32, field_weights [64,64] fp32, out [B,1] fp32.
//
// Round 5: legacy tf32 mma.sync (m16n8k8) Gram GEMM. One warp per batch row.
// G = X X^T over the 20 upper-triangular 16x8 tiles; accumulators in regs;
// epilogue = precomputed masked-W fragments dot acc, warp-reduce.
// Per-warp-private smem staging (8KB) in fragment-permuted k-xor-swizzled
// layout: conflict-free STS.128 writes and LDS.64 fragment reads.

#define NF 64
#define ND 128
#define THREADS 256
#define WPC 8          // warps per CTA
#define NTILES 20

__device__ static const int TI[NTILES] = {0,0,0,0,0,0,0,0, 1,1,1,1,1,1, 2,2,2,2, 3,3};
__device__ static const int TJ[NTILES] = {0,1,2,3,4,5,6,7, 2,3,4,5,6,7, 4,5,6,7, 6,7};

__device__ __forceinline__ uint32_t cvt_tf32(uint32_t fbits) {
    uint32_t r;
    asm("cvt.rna.tf32.f32 %0, %1;" : "=r"(r) : "f"(__uint_as_float(fbits)));
    return r;
}

__device__ __forceinline__ void mma_tf32(float* d,
                                         uint32_t a0, uint32_t a1, uint32_t a2, uint32_t a3,
                                         uint32_t b0, uint32_t b1) {
    asm volatile("mma.sync.aligned.m16n8k8.row.col.f32.tf32.tf32.f32 "
                 "{%0,%1,%2,%3}, {%4,%5,%6,%7}, {%8,%9}, {%0,%1,%2,%3};"
                 : "+f"(d[0]), "+f"(d[1]), "+f"(d[2]), "+f"(d[3])
                 : "r"(a0), "r"(a1), "r"(a2), "r"(a3), "r"(b0), "r"(b1));
}

// Prefetch one 64x32 chunk of X[b] into staging regs as paired LDG.64.
// u (static): s = u>>2 (kstep group), row = (u&3)*16 + (lane>>4)*8 + ((lane>>1)&7).
__device__ __forceinline__ void prefetch(const float* __restrict__ xb, int kbase,
                                         int lane, uint2* stA, uint2* stB) {
    const int m2 = 2 * (lane & 1);
    const int rbase = (lane >> 4) * 8 + ((lane >> 1) & 7);
#pragma unroll
    for (int u = 0; u < 16; ++u) {
        const int s = u >> 2;
        const int row = (u & 3) * 16 + rbase;
        const int pb = m2 ^ (s & 2);
        const uint2* p = (const uint2*)(xb + row * ND + kbase + 8 * s + pb);
        stA[u] = p[0];   // cols pb, pb+1
        stB[u] = p[2];   // cols pb+4, pb+5
    }
}

extern "C" __global__ void __launch_bounds__(THREADS, 1)
wfi_mma(const float* __restrict__ x, const float* __restrict__ fw,
        float* __restrict__ out, int B, int nwarps) {
    extern __shared__ uint32_t smem[];
    const int tid = threadIdx.x, wq = tid >> 5, lane = tid & 31;
    uint32_t* buf = smem + wq * 2048;              // 8KB per-warp staging
    float* wsm = (float*)(smem + WPC * 2048);      // 20*32*4 W fragments (10KB)

    // Precompute masked W fragments: wsm[(t*32+lp)*4 + r].
    for (int idx = tid; idx < NTILES * 128; idx += THREADS) {
        int t = idx >> 7, rem = idx & 127, lp = rem >> 2, r = rem & 3;
        int i = TI[t] * 16 + (lp >> 2) + (r >> 1) * 8;
        int j = TJ[t] * 8 + (lp & 3) * 2 + (r & 1);
        wsm[idx] = (j > i) ? fw[i * NF + j] : 0.0f;
    }
    __syncthreads();

    int b = blockIdx.x * WPC + wq;
    if (b >= B) return;

    uint2 stA[16], stB[16];
    prefetch(x + (size_t)b * (NF * ND), 0, lane, stA, stB);

    float acc[NTILES][4];
#pragma unroll
    for (int t = 0; t < NTILES; ++t)
#pragma unroll
        for (int r = 0; r < 4; ++r) acc[t][r] = 0.0f;

    const int gslot = (lane & 3);
    const int grow  = (lane >> 2) * 8;

    for (;;) {
#pragma unroll 1
        for (int c = 0; c < 4; ++c) {
            __syncwarp();
            // STS staging -> permuted buffer. vec slots: [k0, k0+4, k0^1, k0^1+4].
#pragma unroll
            for (int u = 0; u < 16; ++u) {
                const int s = u >> 2;
                uint32_t a0 = cvt_tf32(stA[u].x), a1 = cvt_tf32(stA[u].y);
                uint32_t b0 = cvt_tf32(stB[u].x), b1 = cvt_tf32(stB[u].y);
                uint4 vec;
                if ((s & 1) == 0) { vec.x = a0; vec.y = b0; vec.z = a1; vec.w = b1; }
                else              { vec.x = a1; vec.y = b1; vec.z = a0; vec.w = b0; }
                ((uint4*)buf)[u * 32 + lane] = vec;
            }
            __syncwarp();

            // Prefetch next chunk (or next b's chunk 0) while mma runs.
            {
                int nc = c + 1, nb = b;
                if (nc == 4) { nc = 0; nb = b + nwarps; }
                if (nb < B)
                    prefetch(x + (size_t)nb * (NF * ND), nc * 32, lane, stA, stB);
            }

            // 4 ksteps x 20 tiles.
#pragma unroll
            for (int s = 0; s < 4; ++s) {
                uint2 g[8];
#pragma unroll
                for (int r = 0; r < 8; ++r) {
                    int w = s * 512 + r * 64 + grow + ((gslot ^ s) << 1);
                    g[r] = *(const uint2*)(buf + w);
                }
#pragma unroll
                for (int t = 0; t < NTILES; ++t) {
                    const int ti = TI[t], tj = TJ[t];
                    mma_tf32(acc[t], g[2 * ti].x, g[2 * ti + 1].x,
                             g[2 * ti].y, g[2 * ti + 1].y, g[tj].x, g[tj].y);
                }
            }
        }

        // Epilogue: weighted reduce of Gram fragments.
        float s = 0.0f;
#pragma unroll
        for (int t = 0; t < NTILES; ++t) {
            float4 w4 = *(const float4*)(wsm + (t * 32 + lane) * 4);
            s = fmaf(w4.x, acc[t][0], s);
            s = fmaf(w4.y, acc[t][1], s);
            s = fmaf(w4.z, acc[t][2], s);
            s = fmaf(w4.w, acc[t][3], s);
#pragma unroll
            for (int r = 0; r < 4; ++r) acc[t][r] = 0.0f;
        }
#pragma unroll
        for (int off = 16; off > 0; off >>= 1)
            s += __shfl_xor_sync(0xFFFFFFFFu, s, off);
        if (lane == 0) out[b] = s;

        b += nwarps;
        if (b >= B) break;
    }
}

extern "C" void kernel_launch(void* const* d_in, const int* in_sizes, int n_in,
                              void* d_out, int out_size) {
    const float* x  = (const float*)d_in[0];
    const float* fw = (const float*)d_in[1];
    float* out      = (float*)d_out;

    int B = in_sizes[0] / (NF * ND);

    int dev = 0, nsm = 148;
    cudaGetDevice(&dev);
    cudaDeviceGetAttribute(&nsm, cudaDevAttrMultiProcessorCount, dev);

    const int smem_bytes = WPC * 2048 * 4 + NTILES * 128 * 4;   // 64KB + 10KB
    cudaFuncSetAttribute(wfi_mma, cudaFuncAttributeMaxDynamicSharedMemorySize, smem_bytes);

    int grid = nsm;
    int nwarps = grid * WPC;
    wfi_mma<<<grid, THREADS, smem_bytes>>>(x, fw, out, B, nwarps);
}

// round 6
// speedup vs baseline: 4.2187x; 1.6842x over previous
#include <cuda_runtime.h>
#include <cstdint>

// WeightedFeatureInteraction: out[b] = sum_{i<j} w[i,j] * <x[b,i,:], x[b,j,:]>
//   inputs [B, 64*128] fp32, field_weights [64,64] fp32, out [B,1] fp32.
//
// Round 6: tf32 mma.sync Gram GEMM (as R5) with a wavefront-minimal staging
// path: coalesced LDG.128 (4 wf/instr, was 16), row-major XOR-swizzled
// STS.128 (conflict-free), swizzled LDS.32 fragment reads (conflict-free).
// One warp per batch row; 20 upper-triangular m16n8k8 tiles; reg accumulators.

#define NF 64
#define ND 128
#define THREADS 256
#define WPC 8
#define NTILES 20

__device__ static const int TI[NTILES] = {0,0,0,0,0,0,0,0, 1,1,1,1,1,1, 2,2,2,2, 3,3};
__device__ static const int TJ[NTILES] = {0,1,2,3,4,5,6,7, 2,3,4,5,6,7, 4,5,6,7, 6,7};

__device__ __forceinline__ uint32_t cvt_tf32(float f) {
    uint32_t r;
    asm("cvt.rna.tf32.f32 %0, %1;" : "=r"(r) : "f"(f));
    return r;
}

__device__ __forceinline__ void mma_tf32(float* d,
                                         uint32_t a0, uint32_t a1, uint32_t a2, uint32_t a3,
                                         uint32_t b0, uint32_t b1) {
    asm volatile("mma.sync.aligned.m16n8k8.row.col.f32.tf32.tf32.f32 "
                 "{%0,%1,%2,%3}, {%4,%5,%6,%7}, {%8,%9}, {%0,%1,%2,%3};"
                 : "+f"(d[0]), "+f"(d[1]), "+f"(d[2]), "+f"(d[3])
                 : "r"(a0), "r"(a1), "r"(a2), "r"(a3), "r"(b0), "r"(b1));
}

// Coalesced prefetch of one 64-row x 32-col chunk: lane l, iter u reads
// float4 at row 4u+(l>>3), cols kbase+(l&7)*4. 4 complete lines per LDG.128.
__device__ __forceinline__ void prefetch(const float* __restrict__ xb, int kbase,
                                         int lane, float4* st) {
    const float* p = xb + (size_t)(lane >> 3) * ND + kbase + (lane & 7) * 4;
#pragma unroll
    for (int u = 0; u < 16; ++u)
        st[u] = *(const float4*)(p + (size_t)(4 * u) * ND);
}

extern "C" __global__ void __launch_bounds__(THREADS, 1)
wfi_mma(const float* __restrict__ x, const float* __restrict__ fw,
        float* __restrict__ out, int B, int nwarps) {
    extern __shared__ uint32_t smem[];
    const int tid = threadIdx.x, wq = tid >> 5, lane = tid & 31;
    uint32_t* buf = smem + wq * 2048;              // 8KB per-warp staging
    float* wsm = (float*)(smem + WPC * 2048);      // 20*32*4 masked W fragments

    // Precompute masked W fragments matching the mma C-fragment layout.
    for (int idx = tid; idx < NTILES * 128; idx += THREADS) {
        int t = idx >> 7, rem = idx & 127, lp = rem >> 2, r = rem & 3;
        int i = TI[t] * 16 + (lp >> 2) + (r >> 1) * 8;
        int j = TJ[t] * 8 + (lp & 3) * 2 + (r & 1);
        wsm[idx] = (j > i) ? fw[i * NF + j] : 0.0f;
    }
    __syncthreads();

    int b = blockIdx.x * WPC + wq;
    if (b >= B) return;

    float4 st[16];
    prefetch(x + (size_t)b * (NF * ND), 0, lane, st);

    float acc[NTILES][4];
#pragma unroll
    for (int t = 0; t < NTILES; ++t)
#pragma unroll
        for (int r = 0; r < 4; ++r) acc[t][r] = 0.0f;

    const int g  = lane >> 2;        // mma group (row within 8-row block)
    const int tg = lane & 3;         // thread-in-group (k within 4)
    const int wrow  = lane >> 3;     // staging write row offset
    const int wcol  = (lane & 7) * 4;

    for (;;) {
#pragma unroll 1
        for (int c = 0; c < 4; ++c) {
            __syncwarp();
            // STS: cvt to tf32, write row-major with col' = col ^ ((row&7)<<2).
#pragma unroll
            for (int u = 0; u < 16; ++u) {
                const int row = 4 * u + wrow;
                const int sc = wcol ^ ((row & 7) << 2);
                uint4 v;
                v.x = cvt_tf32(st[u].x);
                v.y = cvt_tf32(st[u].y);
                v.z = cvt_tf32(st[u].z);
                v.w = cvt_tf32(st[u].w);
                *(uint4*)(buf + row * 32 + sc) = v;
            }
            __syncwarp();

            // Prefetch next chunk (or next b's chunk 0) while mma runs.
            {
                int nc = c + 1, nb = b;
                if (nc == 4) { nc = 0; nb = b + nwarps; }
                if (nb < B)
                    prefetch(x + (size_t)nb * (NF * ND), nc * 32, lane, st);
            }

            // 4 ksteps x 20 tiles. Fragment: fx[r] = x[8r+g][8s+tg] (tf32),
            // fy[r] = x[8r+g][8s+tg+4]. Swizzled conflict-free LDS.32.
#pragma unroll
            for (int s = 0; s < 4; ++s) {
                uint32_t fx[8], fy[8];
#pragma unroll
                for (int r = 0; r < 8; ++r) {
                    const uint32_t base = (8 * r + g) * 32;
                    fx[r] = buf[base + ((8 * s + tg)     ^ (g << 2))];
                    fy[r] = buf[base + ((8 * s + tg + 4) ^ (g << 2))];
                }
#pragma unroll
                for (int t = 0; t < NTILES; ++t) {
                    const int ti = TI[t], tj = TJ[t];
                    mma_tf32(acc[t], fx[2 * ti], fx[2 * ti + 1],
                             fy[2 * ti], fy[2 * ti + 1], fx[tj], fy[tj]);
                }
            }
        }

        // Epilogue: weighted reduce of Gram fragments.
        float s = 0.0f;
#pragma unroll
        for (int t = 0; t < NTILES; ++t) {
            float4 w4 = *(const float4*)(wsm + (t * 32 + lane) * 4);
            s = fmaf(w4.x, acc[t][0], s);
            s = fmaf(w4.y, acc[t][1], s);
            s = fmaf(w4.z, acc[t][2], s);
            s = fmaf(w4.w, acc[t][3], s);
#pragma unroll
            for (int r = 0; r < 4; ++r) acc[t][r] = 0.0f;
        }
#pragma unroll
        for (int off = 16; off > 0; off >>= 1)
            s += __shfl_xor_sync(0xFFFFFFFFu, s, off);
        if (lane == 0) out[b] = s;

        b += nwarps;
        if (b >= B) break;
    }
}

extern "C" void kernel_launch(void* const* d_in, const int* in_sizes, int n_in,
                              void* d_out, int out_size) {
    const float* x  = (const float*)d_in[0];
    const float* fw = (const float*)d_in[1];
    float* out      = (float*)d_out;

    int B = in_sizes[0] / (NF * ND);

    int dev = 0, nsm = 148;
    cudaGetDevice(&dev);
    cudaDeviceGetAttribute(&nsm, cudaDevAttrMultiProcessorCount, dev);

    const int smem_bytes = WPC * 2048 * 4 + NTILES * 128 * 4;   // 64KB + 10KB
    cudaFuncSetAttribute(wfi_mma, cudaFuncAttributeMaxDynamicSharedMemorySize, smem_bytes);

    int grid = nsm;
    int nwarps = grid * WPC;
    wfi_mma<<<grid, THREADS, smem_bytes>>>(x, fw, out, B, nwarps);
}